// round 2
// baseline (speedup 1.0000x reference)
#include <cuda_runtime.h>

#define HORIZON 30
#define DECN    256
#define INDIM   384
#define BMAX    65536

typedef unsigned long long ull;

// gi_base scratch: [B, 768] fp32 (192 MB). Static __device__ per allocation rules.
__device__ float g_gi[(size_t)BMAX * 768];

__device__ __forceinline__ ull pack2(float lo, float hi) {
    ull r; asm("mov.b64 %0, {%1, %2};" : "=l"(r) : "f"(lo), "f"(hi)); return r;
}
__device__ __forceinline__ void ffma2(ull& d, ull a, ull b) {
    asm("fma.rn.f32x2 %0, %1, %2, %0;" : "+l"(d) : "l"(a), "l"(b));
}
__device__ __forceinline__ void unpack2(ull v, float& lo, float& hi) {
    asm("mov.b64 {%0, %1}, %2;" : "=f"(lo), "=f"(hi) : "l"(v));
}
__device__ __forceinline__ float sigf(float x) {
    return __fdividef(1.f, 1.f + __expf(-x));
}
__device__ __forceinline__ float tanh_fast(float x) {
    float t = __expf(2.f * x);                 // x>>0: t=inf -> 1; x<<0: t=0 -> -1
    return 1.f - __fdividef(2.f, t + 1.f);
}

// ---------------- shared memory layout (in floats) ----------------
#define HT_STRIDE 68
#define HT_SIZE   (256 * HT_STRIDE)           // 17408
#define OFF_HT    0                            // 2 buffers (ping-pong)
#define OFF_WT    (2 * HT_SIZE)               // 34816
#define WT_STRIDE 194
#define WT_SIZE   (64 * WT_STRIDE)            // 12416
#define OFF_WMUX  (OFF_WT + WT_SIZE)          // 47232
#define OFF_WMUY  (OFF_WMUX + 768)            // 48000
#define OFF_BHH   (OFF_WMUY + 768)            // 48768
#define OFF_W5    (OFF_BHH + 768)             // 49536 (W_mu 512 + W_cov 768)
#define OFF_MUX   (OFF_W5 + 1280)             // 50816
#define OFF_MUY   (OFF_MUX + 64)              // 50880
#define SMEM_FLOATS (OFF_MUY + 64)            // 50944 floats = 203776 B

#define F4A(arr, expr) { float4 _t4 = (expr); (arr)[0]=_t4.x; (arr)[1]=_t4.y; (arr)[2]=_t4.z; (arr)[3]=_t4.w; }

__global__ void __launch_bounds__(256, 1)
gru_decoder_kernel(const float* __restrict__ zh,  const float* __restrict__ Wh0,
                   const float* __restrict__ bh0, const float* __restrict__ Wih,
                   const float* __restrict__ bih, const float* __restrict__ Whh,
                   const float* __restrict__ bhhg,const float* __restrict__ Wmu,
                   const float* __restrict__ bmu, const float* __restrict__ Wcov,
                   const float* __restrict__ bcov,float* __restrict__ out, int B)
{
    extern __shared__ float sm[];
    float* s_wt   = sm + OFF_WT;
    float* s_wmux = sm + OFF_WMUX;
    float* s_wmuy = sm + OFF_WMUY;
    float* s_bhh  = sm + OFF_BHH;
    float* s_w5   = sm + OFF_W5;
    float* s_mux  = sm + OFF_MUX;
    float* s_muy  = sm + OFF_MUY;

    const int tid = threadIdx.x;
    const int tx = tid & 15, ty = tid >> 4;
    const int j0 = tx * 4, m0 = ty * 4;
    const int b0 = blockIdx.x * 64;

    // ---- one-time small-weight staging ----
    for (int i = tid; i < 768; i += 256) {
        s_wmux[i] = Wih[(size_t)i * 386 + 384];
        s_wmuy[i] = Wih[(size_t)i * 386 + 385];
        s_bhh[i]  = bhhg[i];
    }
    for (int i = tid; i < 512; i += 256) s_w5[i] = Wmu[i];
    for (int i = tid; i < 768; i += 256) s_w5[512 + i] = Wcov[i];
    if (tid < 64) { s_mux[tid] = 0.f; s_muy[tid] = 0.f; }

    // ================= PRECOMPUTE: h0 (-> s_hT buf 0, transposed) and gi_base (-> global) =================
    // C[M=64, 1024] = zh_tile[64,384] @ Wc^T ; Wc rows 0..255 = W_hinit, 256..1023 = W_ih[:, :384]
    float* s_zhT = s_wt;          // [64 k][68], transposed zh chunk
    float* s_wtp = s_wt + 4352;   // [64 k][68], transposed W chunk

    for (int jb = 0; jb < 16; ++jb) {
        ull acc[4][2];
        #pragma unroll
        for (int m = 0; m < 4; ++m) { acc[m][0] = 0ull; acc[m][1] = 0ull; }

        for (int kc = 0; kc < 6; ++kc) {
            __syncthreads();
            #pragma unroll
            for (int it = 0; it < 16; ++it) {
                int idx = it * 256 + tid;
                int kk = idx & 63, rr = idx >> 6;
                s_zhT[kk * 68 + rr] = zh[(size_t)(b0 + rr) * INDIM + kc * 64 + kk];
                int jp = jb * 64 + rr;
                const float* wrow = (jp < 256) ? (Wh0 + (size_t)jp * 384)
                                               : (Wih + (size_t)(jp - 256) * 386);
                s_wtp[kk * 68 + rr] = wrow[kc * 64 + kk];
            }
            __syncthreads();
            #pragma unroll 8
            for (int k = 0; k < 64; ++k) {
                float4 hv = *(const float4*)&s_zhT[k * 68 + m0];
                ull w0 = *(const ull*)&s_wtp[k * 68 + j0];
                ull w1 = *(const ull*)&s_wtp[k * 68 + j0 + 2];
                ull a0 = pack2(hv.x, hv.x), a1 = pack2(hv.y, hv.y);
                ull a2 = pack2(hv.z, hv.z), a3 = pack2(hv.w, hv.w);
                ffma2(acc[0][0], a0, w0); ffma2(acc[0][1], a0, w1);
                ffma2(acc[1][0], a1, w0); ffma2(acc[1][1], a1, w1);
                ffma2(acc[2][0], a2, w0); ffma2(acc[2][1], a2, w1);
                ffma2(acc[3][0], a3, w0); ffma2(acc[3][1], a3, w1);
            }
        }
        float v[4][4];
        #pragma unroll
        for (int m = 0; m < 4; ++m) {
            unpack2(acc[m][0], v[m][0], v[m][1]);
            unpack2(acc[m][1], v[m][2], v[m][3]);
        }
        if (jb < 4) {
            // h0 -> transposed smem buffer 0: h_T[j][m]
            #pragma unroll
            for (int jj = 0; jj < 4; ++jj) {
                int j = jb * 64 + j0 + jj;
                float b = bh0[j];
                *(float4*)&sm[OFF_HT + (size_t)j * HT_STRIDE + m0] =
                    make_float4(v[0][jj] + b, v[1][jj] + b, v[2][jj] + b, v[3][jj] + b);
            }
        } else {
            int gcol = jb * 64 - 256 + j0;
            float4 bb = *(const float4*)&bih[gcol];
            #pragma unroll
            for (int m = 0; m < 4; ++m) {
                *(float4*)&g_gi[(size_t)(b0 + m0 + m) * 768 + gcol] =
                    make_float4(v[m][0] + bb.x, v[m][1] + bb.y, v[m][2] + bb.z, v[m][3] + bb.w);
            }
        }
    }
    __syncthreads();

    const size_t covbase = (size_t)B * HORIZON * 2;

    // ================= 30-step GRU recurrence =================
    int cur = 0;
    for (int t = 0; t < HORIZON; ++t) {
        float* hcur = sm + OFF_HT + cur * HT_SIZE;
        float* hnxt = sm + OFF_HT + (1 - cur) * HT_SIZE;

        for (int jb = 0; jb < 4; ++jb) {
            ull ar[4][2], az[4][2], an[4][2];
            #pragma unroll
            for (int m = 0; m < 4; ++m) {
                ar[m][0]=0ull; ar[m][1]=0ull; az[m][0]=0ull; az[m][1]=0ull; an[m][0]=0ull; an[m][1]=0ull;
            }
            for (int kc = 0; kc < 4; ++kc) {
                __syncthreads();
                // stage W_hh chunk transposed: s_wt[kk][g*64+jj] = Whh[g*256 + jb*64 + jj][kc*64 + kk]
                #pragma unroll
                for (int it = 0; it < 48; ++it) {
                    int idx = it * 256 + tid;
                    int kk = idx & 63; int r = idx >> 6;   // r in [0,192)
                    int g = r >> 6; int jj = r & 63;
                    s_wt[kk * WT_STRIDE + r] =
                        Whh[(size_t)(g * 256 + jb * 64 + jj) * 256 + kc * 64 + kk];
                }
                __syncthreads();
                const float* hbase = hcur + (size_t)(kc * 64) * HT_STRIDE;
                #pragma unroll 8
                for (int k = 0; k < 64; ++k) {
                    float4 hv = *(const float4*)&hbase[k * HT_STRIDE + m0];
                    const float* wr = &s_wt[k * WT_STRIDE];
                    ull wr0 = *(const ull*)&wr[j0],       wr1 = *(const ull*)&wr[j0 + 2];
                    ull wz0 = *(const ull*)&wr[64 + j0],  wz1 = *(const ull*)&wr[64 + j0 + 2];
                    ull wn0 = *(const ull*)&wr[128 + j0], wn1 = *(const ull*)&wr[128 + j0 + 2];
                    ull a0 = pack2(hv.x, hv.x), a1 = pack2(hv.y, hv.y);
                    ull a2 = pack2(hv.z, hv.z), a3 = pack2(hv.w, hv.w);
                    ffma2(ar[0][0], a0, wr0); ffma2(ar[0][1], a0, wr1);
                    ffma2(az[0][0], a0, wz0); ffma2(az[0][1], a0, wz1);
                    ffma2(an[0][0], a0, wn0); ffma2(an[0][1], a0, wn1);
                    ffma2(ar[1][0], a1, wr0); ffma2(ar[1][1], a1, wr1);
                    ffma2(az[1][0], a1, wz0); ffma2(az[1][1], a1, wz1);
                    ffma2(an[1][0], a1, wn0); ffma2(an[1][1], a1, wn1);
                    ffma2(ar[2][0], a2, wr0); ffma2(ar[2][1], a2, wr1);
                    ffma2(az[2][0], a2, wz0); ffma2(az[2][1], a2, wz1);
                    ffma2(an[2][0], a2, wn0); ffma2(an[2][1], a2, wn1);
                    ffma2(ar[3][0], a3, wr0); ffma2(ar[3][1], a3, wr1);
                    ffma2(az[3][0], a3, wz0); ffma2(az[3][1], a3, wz1);
                    ffma2(an[3][0], a3, wn0); ffma2(an[3][1], a3, wn1);
                }
            }
            // ---- gate epilogue for this j-block ----
            const int jbase = jb * 64 + j0;   // hidden index in [0,256)
            float wmxr[4], wmxz[4], wmxn[4], wmyr[4], wmyz[4], wmyn[4];
            float bhr[4], bhz[4], bhn[4];
            F4A(wmxr, *(const float4*)&s_wmux[jbase]);
            F4A(wmxz, *(const float4*)&s_wmux[256 + jbase]);
            F4A(wmxn, *(const float4*)&s_wmux[512 + jbase]);
            F4A(wmyr, *(const float4*)&s_wmuy[jbase]);
            F4A(wmyz, *(const float4*)&s_wmuy[256 + jbase]);
            F4A(wmyn, *(const float4*)&s_wmuy[512 + jbase]);
            F4A(bhr,  *(const float4*)&s_bhh[jbase]);
            F4A(bhz,  *(const float4*)&s_bhh[256 + jbase]);
            F4A(bhn,  *(const float4*)&s_bhh[512 + jbase]);

            float ho[4][4];   // [jj][m]
            #pragma unroll
            for (int jj = 0; jj < 4; ++jj)
                F4A(ho[jj], *(const float4*)&hcur[(size_t)(jbase + jj) * HT_STRIDE + m0]);

            float hnew[4][4]; // [m][jj]
            #pragma unroll
            for (int m = 0; m < 4; ++m) {
                const float* gib = &g_gi[(size_t)(b0 + m0 + m) * 768 + jbase];
                float gr[4], gz[4], gn[4];
                F4A(gr, *(const float4*)gib);
                F4A(gz, *(const float4*)(gib + 256));
                F4A(gn, *(const float4*)(gib + 512));
                float mx = s_mux[m0 + m], my = s_muy[m0 + m];
                float rr[4], zz[4], nn[4];
                unpack2(ar[m][0], rr[0], rr[1]); unpack2(ar[m][1], rr[2], rr[3]);
                unpack2(az[m][0], zz[0], zz[1]); unpack2(az[m][1], zz[2], zz[3]);
                unpack2(an[m][0], nn[0], nn[1]); unpack2(an[m][1], nn[2], nn[3]);
                #pragma unroll
                for (int jj = 0; jj < 4; ++jj) {
                    float gi_r = gr[jj] + mx * wmxr[jj] + my * wmyr[jj];
                    float gi_z = gz[jj] + mx * wmxz[jj] + my * wmyz[jj];
                    float gi_n = gn[jj] + mx * wmxn[jj] + my * wmyn[jj];
                    float r  = sigf(gi_r + rr[jj] + bhr[jj]);
                    float zg = sigf(gi_z + zz[jj] + bhz[jj]);
                    float n  = tanh_fast(gi_n + r * (nn[jj] + bhn[jj]));
                    hnew[m][jj] = (1.f - zg) * n + zg * ho[jj][m];
                }
            }
            #pragma unroll
            for (int jj = 0; jj < 4; ++jj)
                *(float4*)&hnxt[(size_t)(jbase + jj) * HT_STRIDE + m0] =
                    make_float4(hnew[0][jj], hnew[1][jj], hnew[2][jj], hnew[3][jj]);
        } // jb

        __syncthreads();   // hnxt fully written

        // ---- mu / cov epilogue: 5 dots of length 256 per batch row ----
        #pragma unroll
        for (int pass = 0; pass < 2; ++pass) {
            int task = pass * 256 + tid;
            if (task < 320) {
                int o = task >> 6; int m = task & 63;
                const float* wrow = &s_w5[o * 256];
                const float* hc = &hnxt[m];
                float acc = 0.f;
                #pragma unroll 8
                for (int k = 0; k < 256; ++k) acc += hc[(size_t)k * HT_STRIDE] * wrow[k];
                size_t idx2 = ((size_t)(b0 + m) * HORIZON + t);
                if (o == 0) {
                    float vv = acc + bmu[0]; out[idx2 * 2]     = vv; s_mux[m] = vv;
                } else if (o == 1) {
                    float vv = acc + bmu[1]; out[idx2 * 2 + 1] = vv; s_muy[m] = vv;
                } else if (o == 2) {
                    float vv = fminf(fmaxf(acc + bcov[0], 0.2f), 1.0f);
                    out[covbase + idx2 * 4]     = vv;
                } else if (o == 3) {
                    float vv = fminf(fmaxf(acc + bcov[1], -0.1f), 0.1f);
                    out[covbase + idx2 * 4 + 1] = vv;
                    out[covbase + idx2 * 4 + 2] = vv;
                } else {
                    float vv = fminf(fmaxf(acc + bcov[2], 0.2f), 1.0f);
                    out[covbase + idx2 * 4 + 3] = vv;
                }
            }
        }
        cur ^= 1;
        // next step's first __syncthreads() (inside kc loop) orders s_mux/s_muy + buffers
    }
}

extern "C" void kernel_launch(void* const* d_in, const int* in_sizes, int n_in,
                              void* d_out, int out_size) {
    const float* zh   = (const float*)d_in[0];
    const float* Wh0  = (const float*)d_in[1];
    const float* bh0  = (const float*)d_in[2];
    const float* Wih  = (const float*)d_in[3];
    const float* bih  = (const float*)d_in[4];
    const float* Whh  = (const float*)d_in[5];
    const float* bhh  = (const float*)d_in[6];
    const float* Wmu  = (const float*)d_in[7];
    const float* bmu  = (const float*)d_in[8];
    const float* Wcov = (const float*)d_in[9];
    const float* bcov = (const float*)d_in[10];
    float* out = (float*)d_out;

    int B = in_sizes[0] / INDIM;
    cudaFuncSetAttribute(gru_decoder_kernel,
                         cudaFuncAttributeMaxDynamicSharedMemorySize, SMEM_FLOATS * 4);
    gru_decoder_kernel<<<B / 64, 256, SMEM_FLOATS * 4>>>(
        zh, Wh0, bh0, Wih, bih, Whh, bhh, Wmu, bmu, Wcov, bcov, out, B);
}

// round 3
// speedup vs baseline: 1.2705x; 1.2705x over previous
#include <cuda_runtime.h>
#include <cstdint>

#define HORIZON 30
#define INDIM   384
#define BMAX    65536

typedef unsigned long long ull;

// gi_base scratch: [B, 768] fp32 (192 MB) static device scratch.
__device__ float g_gi[(size_t)BMAX * 768];

__device__ __forceinline__ ull pack2(float lo, float hi) {
    ull r; asm("mov.b64 %0, {%1, %2};" : "=l"(r) : "f"(lo), "f"(hi)); return r;
}
__device__ __forceinline__ void ffma2(ull& d, ull a, ull b) {
    asm("fma.rn.f32x2 %0, %1, %2, %0;" : "+l"(d) : "l"(a), "l"(b));
}
__device__ __forceinline__ void unpack2(ull v, float& lo, float& hi) {
    asm("mov.b64 {%0, %1}, %2;" : "=f"(lo), "=f"(hi) : "l"(v));
}
__device__ __forceinline__ float sigf(float x) {
    return __fdividef(1.f, 1.f + __expf(-x));
}
__device__ __forceinline__ float tanh_fast(float x) {
    float t = __expf(2.f * x);
    return 1.f - __fdividef(2.f, t + 1.f);
}

__device__ __forceinline__ void cpa16(uint32_t s, const void* g) {
    asm volatile("cp.async.cg.shared.global [%0], [%1], 16;" :: "r"(s), "l"(g));
}
#define CPA_COMMIT() asm volatile("cp.async.commit_group;")
#define CPA_WAIT1()  asm volatile("cp.async.wait_group 1;")
#define CPA_WAIT0()  asm volatile("cp.async.wait_group 0;")

// ---------------- shared memory layout (floats) ----------------
#define HT_STRIDE 68
#define HT_SIZE   (256 * HT_STRIDE)          // 17408
#define OFF_HT    0                           // 2 ping-pong buffers
#define OFF_W     (2 * HT_SIZE)              // 34816
#define W_ROWPAD  20                          // 16 k + 4 pad (conflict-free LDS.128)
#define W_BUF     (384 * W_ROWPAD)           // 7680 floats per buffer
#define OFF_WMUX  (OFF_W + 2 * W_BUF)        // 50176
#define OFF_WMUY  (OFF_WMUX + 768)           // 50944
#define OFF_BHH   (OFF_WMUY + 768)           // 51712
#define OFF_W5    (OFF_BHH + 768)            // 52480
#define OFF_MUX   (OFF_W5 + 1280)            // 53760
#define OFF_MUY   (OFF_MUX + 64)             // 53824
#define SMEM_FLOATS (OFF_MUY + 64)           // 53888 floats = 215552 B

#define F4A(arr, expr) { float4 _t4 = (expr); (arr)[0]=_t4.x; (arr)[1]=_t4.y; (arr)[2]=_t4.z; (arr)[3]=_t4.w; }

// Issue one 16-k W chunk (24 KB) via cp.async into buffer (c&1).
// Row permutation: smem row r = g*128 + (tx + jj*32) holds j_local = 4*tx + jj,
// so compute-side LDS.128 across lanes tx is bank-conflict-free (stride 20 floats).
__device__ __forceinline__ void issue_chunk(uint32_t s_w_u32, const float* __restrict__ Whh,
                                            int c, int tid) {
    const int jb = (c >> 4) & 1;
    const int kc = c & 15;
    const uint32_t sbuf = s_w_u32 + (uint32_t)((c & 1) * W_BUF * 4);
    #pragma unroll
    for (int o = 0; o < 6; ++o) {
        int idx = o * 256 + tid;            // 0..1535
        int r = idx >> 2, q = idx & 3;      // r: smem row, q: 16B quad within row
        int g = r >> 7, rl = r & 127;
        int jl = ((rl & 31) << 2) | (rl >> 5);
        const float* gp = Whh + (size_t)(g * 256 + jb * 128 + jl) * 256 + kc * 16 + q * 4;
        cpa16(sbuf + (uint32_t)((r * W_ROWPAD + q * 4) * 4), gp);
    }
}

__global__ void __launch_bounds__(256, 1)
gru_decoder_kernel(const float* __restrict__ zh,  const float* __restrict__ Wh0,
                   const float* __restrict__ bh0, const float* __restrict__ Wih,
                   const float* __restrict__ bih, const float* __restrict__ Whh,
                   const float* __restrict__ bhhg,const float* __restrict__ Wmu,
                   const float* __restrict__ bmu, const float* __restrict__ Wcov,
                   const float* __restrict__ bcov,float* __restrict__ out, int B)
{
    extern __shared__ float sm[];
    float* s_w    = sm + OFF_W;
    float* s_wmux = sm + OFF_WMUX;
    float* s_wmuy = sm + OFF_WMUY;
    float* s_bhh  = sm + OFF_BHH;
    float* s_w5   = sm + OFF_W5;
    float* s_mux  = sm + OFF_MUX;
    float* s_muy  = sm + OFF_MUY;

    const int tid = threadIdx.x;
    const int tx = tid & 31, ty = tid >> 5;     // warp == one ty -> h loads broadcast
    const int j0 = tx * 4, m0 = ty * 8;
    const int b0 = blockIdx.x * 64;

    const uint32_t s_w_u32 = (uint32_t)__cvta_generic_to_shared(s_w);

    // ---- one-time small-weight staging ----
    for (int i = tid; i < 768; i += 256) {
        s_wmux[i] = Wih[(size_t)i * 386 + 384];
        s_wmuy[i] = Wih[(size_t)i * 386 + 385];
        s_bhh[i]  = bhhg[i];
    }
    for (int i = tid; i < 512; i += 256) s_w5[i] = Wmu[i];
    for (int i = tid; i < 768; i += 256) s_w5[512 + i] = Wcov[i];
    if (tid < 64) { s_mux[tid] = 0.f; s_muy[tid] = 0.f; }

    // ================= PRECOMPUTE: h0 (buf 0, transposed) and gi_base (global) ==========
    {
        const int tx4 = tid & 15, ty4 = tid >> 4;
        const int j04 = tx4 * 4, m04 = ty4 * 4;
        float* s_zhT = s_w;          // [64 k][68]
        float* s_wtp = s_w + 4352;   // [64 k][68]

        for (int jb = 0; jb < 16; ++jb) {
            ull acc[4][2];
            #pragma unroll
            for (int m = 0; m < 4; ++m) { acc[m][0] = 0ull; acc[m][1] = 0ull; }

            for (int kc = 0; kc < 6; ++kc) {
                __syncthreads();
                #pragma unroll
                for (int it = 0; it < 16; ++it) {
                    int idx = it * 256 + tid;
                    int kk = idx & 63, rr = idx >> 6;
                    s_zhT[kk * 68 + rr] = zh[(size_t)(b0 + rr) * INDIM + kc * 64 + kk];
                    int jp = jb * 64 + rr;
                    const float* wrow = (jp < 256) ? (Wh0 + (size_t)jp * 384)
                                                   : (Wih + (size_t)(jp - 256) * 386);
                    s_wtp[kk * 68 + rr] = wrow[kc * 64 + kk];
                }
                __syncthreads();
                #pragma unroll 8
                for (int k = 0; k < 64; ++k) {
                    float4 hv = *(const float4*)&s_zhT[k * 68 + m04];
                    ull w0 = *(const ull*)&s_wtp[k * 68 + j04];
                    ull w1 = *(const ull*)&s_wtp[k * 68 + j04 + 2];
                    ull a0 = pack2(hv.x, hv.x), a1 = pack2(hv.y, hv.y);
                    ull a2 = pack2(hv.z, hv.z), a3 = pack2(hv.w, hv.w);
                    ffma2(acc[0][0], a0, w0); ffma2(acc[0][1], a0, w1);
                    ffma2(acc[1][0], a1, w0); ffma2(acc[1][1], a1, w1);
                    ffma2(acc[2][0], a2, w0); ffma2(acc[2][1], a2, w1);
                    ffma2(acc[3][0], a3, w0); ffma2(acc[3][1], a3, w1);
                }
            }
            float v[4][4];
            #pragma unroll
            for (int m = 0; m < 4; ++m) {
                unpack2(acc[m][0], v[m][0], v[m][1]);
                unpack2(acc[m][1], v[m][2], v[m][3]);
            }
            if (jb < 4) {
                #pragma unroll
                for (int jj = 0; jj < 4; ++jj) {
                    int j = jb * 64 + j04 + jj;
                    float b = bh0[j];
                    *(float4*)&sm[OFF_HT + (size_t)j * HT_STRIDE + m04] =
                        make_float4(v[0][jj] + b, v[1][jj] + b, v[2][jj] + b, v[3][jj] + b);
                }
            } else {
                int gcol = jb * 64 - 256 + j04;
                float4 bb = *(const float4*)&bih[gcol];
                #pragma unroll
                for (int m = 0; m < 4; ++m) {
                    *(float4*)&g_gi[(size_t)(b0 + m04 + m) * 768 + gcol] =
                        make_float4(v[m][0] + bb.x, v[m][1] + bb.y, v[m][2] + bb.z, v[m][3] + bb.w);
                }
            }
        }
        __syncthreads();
    }

    const size_t covbase = (size_t)B * HORIZON * 2;

    // Prime the W pipeline: chunk 0
    issue_chunk(s_w_u32, Whh, 0, tid);
    CPA_COMMIT();

    // ================= 30-step GRU recurrence =================
    int cur = 0;
    #pragma unroll 1
    for (int t = 0; t < HORIZON; ++t) {
        float* hcur = sm + OFF_HT + cur * HT_SIZE;
        float* hnxt = sm + OFF_HT + (1 - cur) * HT_SIZE;

        #pragma unroll 1
        for (int jb = 0; jb < 2; ++jb) {
            const int jbase = jb * 128 + j0;

            // acc[jj][mpair] per gate, pre-seeded with b_hh (same bias for all m)
            ull aR[4][4], aZ[4][4], aN[4][4];
            {
                float4 br4 = *(const float4*)&s_bhh[jbase];
                float4 bz4 = *(const float4*)&s_bhh[256 + jbase];
                float4 bn4 = *(const float4*)&s_bhh[512 + jbase];
                const float* brp = (const float*)&br4;
                const float* bzp = (const float*)&bz4;
                const float* bnp = (const float*)&bn4;
                #pragma unroll
                for (int jj = 0; jj < 4; ++jj) {
                    ull br = pack2(brp[jj], brp[jj]);
                    ull bz = pack2(bzp[jj], bzp[jj]);
                    ull bn = pack2(bnp[jj], bnp[jj]);
                    #pragma unroll
                    for (int mp = 0; mp < 4; ++mp) { aR[jj][mp]=br; aZ[jj][mp]=bz; aN[jj][mp]=bn; }
                }
            }

            #pragma unroll 1
            for (int kc = 0; kc < 16; ++kc) {
                const int c = jb * 16 + kc;
                issue_chunk(s_w_u32, Whh, (c + 1) & 31, tid);
                CPA_COMMIT();
                CPA_WAIT1();               // chunk c fully landed (this thread's part)
                __syncthreads();           // everyone's part landed

                const float* wb  = s_w + (c & 1) * W_BUF;
                const float* hch = hcur + (size_t)(kc * 16) * HT_STRIDE + m0;

                #pragma unroll
                for (int kg = 0; kg < 4; ++kg) {
                    float4 w4r[4], w4z[4], w4n[4];
                    #pragma unroll
                    for (int jj = 0; jj < 4; ++jj) {
                        int rbase = tx + jj * 32;
                        w4r[jj] = *(const float4*)&wb[(      rbase) * W_ROWPAD + kg * 4];
                        w4z[jj] = *(const float4*)&wb[(128 + rbase) * W_ROWPAD + kg * 4];
                        w4n[jj] = *(const float4*)&wb[(256 + rbase) * W_ROWPAD + kg * 4];
                    }
                    #pragma unroll
                    for (int kk = 0; kk < 4; ++kk) {
                        const float* hr = hch + (size_t)(kg * 4 + kk) * HT_STRIDE;
                        ulonglong2 q0 = *(const ulonglong2*)hr;        // (m0,m0+1),(m0+2,m0+3)
                        ulonglong2 q1 = *(const ulonglong2*)(hr + 4);  // (m0+4..m0+7)
                        ull a0 = q0.x, a1 = q0.y, a2 = q1.x, a3 = q1.y;
                        #pragma unroll
                        for (int jj = 0; jj < 4; ++jj) {
                            float wr = ((const float*)&w4r[jj])[kk];
                            float wz = ((const float*)&w4z[jj])[kk];
                            float wn = ((const float*)&w4n[jj])[kk];
                            ull br = pack2(wr, wr), bz = pack2(wz, wz), bn = pack2(wn, wn);
                            ffma2(aR[jj][0], a0, br); ffma2(aR[jj][1], a1, br);
                            ffma2(aR[jj][2], a2, br); ffma2(aR[jj][3], a3, br);
                            ffma2(aZ[jj][0], a0, bz); ffma2(aZ[jj][1], a1, bz);
                            ffma2(aZ[jj][2], a2, bz); ffma2(aZ[jj][3], a3, bz);
                            ffma2(aN[jj][0], a0, bn); ffma2(aN[jj][1], a1, bn);
                            ffma2(aN[jj][2], a2, bn); ffma2(aN[jj][3], a3, bn);
                        }
                    }
                }
                __syncthreads();           // done reading buf (c&1) before it's re-issued
            }

            // ---- gate epilogue for this j-block ----
            float fR[4][8], fZ[4][8], fN[4][8];
            #pragma unroll
            for (int jj = 0; jj < 4; ++jj)
                #pragma unroll
                for (int mp = 0; mp < 4; ++mp) {
                    unpack2(aR[jj][mp], fR[jj][2*mp], fR[jj][2*mp+1]);
                    unpack2(aZ[jj][mp], fZ[jj][2*mp], fZ[jj][2*mp+1]);
                    unpack2(aN[jj][mp], fN[jj][2*mp], fN[jj][2*mp+1]);
                }

            float ho[4][8];
            #pragma unroll
            for (int jj = 0; jj < 4; ++jj) {
                const float* hp = &hcur[(size_t)(jbase + jj) * HT_STRIDE + m0];
                float4 o0 = *(const float4*)hp;
                float4 o1 = *(const float4*)(hp + 4);
                ho[jj][0]=o0.x; ho[jj][1]=o0.y; ho[jj][2]=o0.z; ho[jj][3]=o0.w;
                ho[jj][4]=o1.x; ho[jj][5]=o1.y; ho[jj][6]=o1.z; ho[jj][7]=o1.w;
            }

            float wmx[3][4], wmy[3][4];
            #pragma unroll
            for (int g = 0; g < 3; ++g) {
                F4A(wmx[g], *(const float4*)&s_wmux[g * 256 + jbase]);
                F4A(wmy[g], *(const float4*)&s_wmuy[g * 256 + jbase]);
            }

            #pragma unroll
            for (int m = 0; m < 8; ++m) {
                const float* gp = &g_gi[(size_t)(b0 + m0 + m) * 768 + jbase];
                float4 gr = *(const float4*)gp;
                float4 gz = *(const float4*)(gp + 256);
                float4 gn = *(const float4*)(gp + 512);
                const float* grp = (const float*)&gr;
                const float* gzp = (const float*)&gz;
                const float* gnp = (const float*)&gn;
                float mx = s_mux[m0 + m], my = s_muy[m0 + m];
                #pragma unroll
                for (int jj = 0; jj < 4; ++jj) {
                    float gi_r = grp[jj] + mx * wmx[0][jj] + my * wmy[0][jj];
                    float gi_z = gzp[jj] + mx * wmx[1][jj] + my * wmy[1][jj];
                    float gi_n = gnp[jj] + mx * wmx[2][jj] + my * wmy[2][jj];
                    float r  = sigf(gi_r + fR[jj][m]);
                    float z  = sigf(gi_z + fZ[jj][m]);
                    float n  = tanh_fast(gi_n + r * fN[jj][m]);
                    fR[jj][m] = (1.f - z) * n + z * ho[jj][m];   // reuse fR as h_new
                }
            }

            #pragma unroll
            for (int jj = 0; jj < 4; ++jj) {
                float* hp = &hnxt[(size_t)(jbase + jj) * HT_STRIDE + m0];
                *(float4*)hp       = make_float4(fR[jj][0], fR[jj][1], fR[jj][2], fR[jj][3]);
                *(float4*)(hp + 4) = make_float4(fR[jj][4], fR[jj][5], fR[jj][6], fR[jj][7]);
            }
        } // jb

        __syncthreads();   // hnxt fully written

        // ---- mu / cov epilogue: 5 dots of length 256 per batch row ----
        #pragma unroll
        for (int pass = 0; pass < 2; ++pass) {
            int task = pass * 256 + tid;
            if (task < 320) {
                int o = task >> 6; int m = task & 63;
                const float* wrow = &s_w5[o * 256];
                const float* hc = sm + OFF_HT + (1 - cur) * HT_SIZE + m;
                float acc = 0.f;
                #pragma unroll 8
                for (int k = 0; k < 256; ++k) acc += hc[(size_t)k * HT_STRIDE] * wrow[k];
                size_t idx2 = ((size_t)(b0 + m) * HORIZON + t);
                if (o == 0) {
                    float vv = acc + bmu[0]; out[idx2 * 2]     = vv; s_mux[m] = vv;
                } else if (o == 1) {
                    float vv = acc + bmu[1]; out[idx2 * 2 + 1] = vv; s_muy[m] = vv;
                } else if (o == 2) {
                    float vv = fminf(fmaxf(acc + bcov[0], 0.2f), 1.0f);
                    out[covbase + idx2 * 4]     = vv;
                } else if (o == 3) {
                    float vv = fminf(fmaxf(acc + bcov[1], -0.1f), 0.1f);
                    out[covbase + idx2 * 4 + 1] = vv;
                    out[covbase + idx2 * 4 + 2] = vv;
                } else {
                    float vv = fminf(fmaxf(acc + bcov[2], 0.2f), 1.0f);
                    out[covbase + idx2 * 4 + 3] = vv;
                }
            }
        }
        cur ^= 1;
        // next step's first chunk __syncthreads orders s_mux/s_muy + buffers
    }

    CPA_WAIT0();   // drain the speculative final prefetch before exit
}

extern "C" void kernel_launch(void* const* d_in, const int* in_sizes, int n_in,
                              void* d_out, int out_size) {
    const float* zh   = (const float*)d_in[0];
    const float* Wh0  = (const float*)d_in[1];
    const float* bh0  = (const float*)d_in[2];
    const float* Wih  = (const float*)d_in[3];
    const float* bih  = (const float*)d_in[4];
    const float* Whh  = (const float*)d_in[5];
    const float* bhh  = (const float*)d_in[6];
    const float* Wmu  = (const float*)d_in[7];
    const float* bmu  = (const float*)d_in[8];
    const float* Wcov = (const float*)d_in[9];
    const float* bcov = (const float*)d_in[10];
    float* out = (float*)d_out;

    int B = in_sizes[0] / INDIM;
    cudaFuncSetAttribute(gru_decoder_kernel,
                         cudaFuncAttributeMaxDynamicSharedMemorySize, SMEM_FLOATS * 4);
    gru_decoder_kernel<<<B / 64, 256, SMEM_FLOATS * 4>>>(
        zh, Wh0, bh0, Wih, bih, Whh, bhh, Wmu, bmu, Wcov, bcov, out, B);
}